// round 1
// baseline (speedup 1.0000x reference)
#include <cuda_runtime.h>
#include <cstdint>

#define B_ROWS 4096
#define D_DIM  768
#define F_DIM  24576
#define TOPK   32

// ---------------- scratch (device globals; no runtime allocation) ----------
__device__ float g_tv[B_ROWS * TOPK];
__device__ int   g_ti[B_ROWS * TOPK];
// fallback scratch for pre-activations if d_out cannot hold H
__device__ float g_H[(size_t)B_ROWS * F_DIM];

// ---------------------------------------------------------------------------
// Encoder GEMM: H = relu((x - b_pre) @ W_enc + b_enc)
// BM=128, BN=128, BK=16, 256 threads, 8x8 per-thread tile, fp32x2 packed FFMA.
// grid = (B/128 rowTiles, F/128 colTiles); x-major order => consecutive CTAs
// share the same W_enc column tile (L2 reuse), x stays resident in L2.
// ---------------------------------------------------------------------------
__global__ __launch_bounds__(256, 2)
void enc_gemm(const float* __restrict__ X, const float* __restrict__ b_pre,
              const float* __restrict__ W, const float* __restrict__ b_enc,
              float* __restrict__ H)
{
    __shared__ float As[16][132];   // transposed A tile, +4 pad (16B-aligned rows)
    __shared__ float Bs[16][128];

    const int tid  = threadIdx.x;
    const int row0 = blockIdx.x * 128;
    const int col0 = blockIdx.y * 128;
    const int tx = tid & 15;        // 0..15 -> 8 cols each
    const int ty = tid >> 4;        // 0..15 -> 8 rows each

    const int alr = tid >> 2;       // A loader: row 0..63 (and +64)
    const int ac4 = tid & 3;        // A loader: which float4 along K
    const int blr = tid >> 5;       // B loader: k-row 0..7 (and +8)
    const int bc4 = tid & 31;       // B loader: float4 along N

    uint64_t acc[32];               // [mp(4 M-pairs)][n(8)] packed f32x2 along M
    #pragma unroll
    for (int i = 0; i < 32; i++) acc[i] = 0ull;

    for (int k0 = 0; k0 < D_DIM; k0 += 16) {
        // ---- load A tile (128x16), subtract b_pre, store transposed ----
        float4 bp = *reinterpret_cast<const float4*>(b_pre + k0 + ac4 * 4);
        #pragma unroll
        for (int rr = 0; rr < 2; rr++) {
            int r = alr + rr * 64;
            float4 av = *reinterpret_cast<const float4*>(
                X + (size_t)(row0 + r) * D_DIM + k0 + ac4 * 4);
            As[ac4 * 4 + 0][r] = av.x - bp.x;
            As[ac4 * 4 + 1][r] = av.y - bp.y;
            As[ac4 * 4 + 2][r] = av.z - bp.z;
            As[ac4 * 4 + 3][r] = av.w - bp.w;
        }
        // ---- load B tile (16x128) ----
        #pragma unroll
        for (int rr = 0; rr < 2; rr++) {
            int r = blr + rr * 8;
            *reinterpret_cast<float4*>(&Bs[r][bc4 * 4]) =
                *reinterpret_cast<const float4*>(
                    W + (size_t)(k0 + r) * F_DIM + col0 + bc4 * 4);
        }
        __syncthreads();

        #pragma unroll
        for (int k = 0; k < 16; k++) {
            // A fragment: 8 consecutive rows -> 4 natural f32x2 pairs
            ulonglong2 aA = *reinterpret_cast<const ulonglong2*>(&As[k][ty * 8]);
            ulonglong2 aB = *reinterpret_cast<const ulonglong2*>(&As[k][ty * 8 + 4]);
            uint64_t a2[4] = {aA.x, aA.y, aB.x, aB.y};
            // B fragment: 8 cols, broadcast each into both packed halves
            float4 b0 = *reinterpret_cast<const float4*>(&Bs[k][tx * 8]);
            float4 b1 = *reinterpret_cast<const float4*>(&Bs[k][tx * 8 + 4]);
            uint64_t b2[8];
            asm("mov.b64 %0, {%1, %1};" : "=l"(b2[0]) : "r"(__float_as_uint(b0.x)));
            asm("mov.b64 %0, {%1, %1};" : "=l"(b2[1]) : "r"(__float_as_uint(b0.y)));
            asm("mov.b64 %0, {%1, %1};" : "=l"(b2[2]) : "r"(__float_as_uint(b0.z)));
            asm("mov.b64 %0, {%1, %1};" : "=l"(b2[3]) : "r"(__float_as_uint(b0.w)));
            asm("mov.b64 %0, {%1, %1};" : "=l"(b2[4]) : "r"(__float_as_uint(b1.x)));
            asm("mov.b64 %0, {%1, %1};" : "=l"(b2[5]) : "r"(__float_as_uint(b1.y)));
            asm("mov.b64 %0, {%1, %1};" : "=l"(b2[6]) : "r"(__float_as_uint(b1.z)));
            asm("mov.b64 %0, {%1, %1};" : "=l"(b2[7]) : "r"(__float_as_uint(b1.w)));
            #pragma unroll
            for (int mp = 0; mp < 4; mp++) {
                #pragma unroll
                for (int n = 0; n < 8; n++) {
                    asm("fma.rn.f32x2 %0, %1, %2, %0;"
                        : "+l"(acc[mp * 8 + n]) : "l"(a2[mp]), "l"(b2[n]));
                }
            }
        }
        __syncthreads();
    }

    // ---- epilogue: + b_enc, relu, vectorized store ----
    float4 be0 = *reinterpret_cast<const float4*>(b_enc + col0 + tx * 8);
    float4 be1 = *reinterpret_cast<const float4*>(b_enc + col0 + tx * 8 + 4);
    float ben[8] = {be0.x, be0.y, be0.z, be0.w, be1.x, be1.y, be1.z, be1.w};

    #pragma unroll
    for (int mp = 0; mp < 4; mp++) {
        float lo[8], hi[8];
        #pragma unroll
        for (int n = 0; n < 8; n++) {
            uint64_t p = acc[mp * 8 + n];
            lo[n] = fmaxf(__uint_as_float((uint32_t)p) + ben[n], 0.0f);
            hi[n] = fmaxf(__uint_as_float((uint32_t)(p >> 32)) + ben[n], 0.0f);
        }
        size_t rlo = (size_t)(row0 + ty * 8 + 2 * mp) * F_DIM + col0 + tx * 8;
        size_t rhi = rlo + F_DIM;
        *reinterpret_cast<float4*>(H + rlo)     = make_float4(lo[0], lo[1], lo[2], lo[3]);
        *reinterpret_cast<float4*>(H + rlo + 4) = make_float4(lo[4], lo[5], lo[6], lo[7]);
        *reinterpret_cast<float4*>(H + rhi)     = make_float4(hi[0], hi[1], hi[2], hi[3]);
        *reinterpret_cast<float4*>(H + rhi + 4) = make_float4(hi[4], hi[5], hi[6], hi[7]);
    }
}

// ---------------------------------------------------------------------------
// Per-row top-32: iterative argmax with cached per-thread local max.
// Thread t owns indices {j*256 + t : j<96}. After selection, the row is
// rewritten in-place (zeros everywhere, winners scattered back).
// Ties resolved toward lower index (matches jax.lax.top_k).
// ---------------------------------------------------------------------------
__global__ __launch_bounds__(256)
void topk_kernel(float* __restrict__ H)
{
    const int row = blockIdx.x;
    float* __restrict__ hrow = H + (size_t)row * F_DIM;
    const int t = threadIdx.x;
    const int lane = t & 31, warp = t >> 5;

    __shared__ float swv[8];
    __shared__ int   swi[8];
    __shared__ int   s_ci;
    __shared__ float s_val[TOPK];
    __shared__ int   s_idx[TOPK];

    uint64_t rem0 = 0ull, rem1 = 0ull;     // removed bits for my 96 slots
    float lmax = -1.0f; int lidx = 0x7fffffff;
    for (int j = 0; j < 96; j++) {
        float v = hrow[j * 256 + t];
        if (v > lmax) { lmax = v; lidx = j * 256 + t; }
    }

    for (int r = 0; r < TOPK; r++) {
        // warp-level argmax (lower index wins ties)
        float v = lmax; int id = lidx;
        #pragma unroll
        for (int s = 16; s > 0; s >>= 1) {
            float ov = __shfl_down_sync(0xffffffffu, v, s);
            int   oi = __shfl_down_sync(0xffffffffu, id, s);
            if (ov > v || (ov == v && oi < id)) { v = ov; id = oi; }
        }
        if (lane == 0) { swv[warp] = v; swi[warp] = id; }
        __syncthreads();
        if (t == 0) {
            float bv = swv[0]; int bi = swi[0];
            #pragma unroll
            for (int w = 1; w < 8; w++)
                if (swv[w] > bv || (swv[w] == bv && swi[w] < bi)) { bv = swv[w]; bi = swi[w]; }
            s_ci = bi; s_val[r] = bv; s_idx[r] = bi;
        }
        __syncthreads();
        int wi = s_ci;
        if ((wi & 255) == t) {              // I own the winner: remove + rescan
            int j = wi >> 8;
            if (j < 64) rem0 |= (1ull << j); else rem1 |= (1ull << (j - 64));
            lmax = -1.0f; lidx = 0x7fffffff;
            for (int j2 = 0; j2 < 96; j2++) {
                bool rm = (j2 < 64) ? ((rem0 >> j2) & 1ull) : ((rem1 >> (j2 - 64)) & 1ull);
                float vv = hrow[j2 * 256 + t];
                if (!rm && vv > lmax) { lmax = vv; lidx = j2 * 256 + t; }
            }
        }
        __syncthreads();
    }

    if (t < TOPK) {
        g_tv[row * TOPK + t] = s_val[t];
        g_ti[row * TOPK + t] = s_idx[t];
    }
    __syncthreads();
    for (int j = 0; j < 96; j++) hrow[j * 256 + t] = 0.0f;
    __syncthreads();
    if (t < TOPK) hrow[s_idx[t]] = s_val[t];
}

// ---------------------------------------------------------------------------
// Decoder: x_hat[row] = sum_j val_j * W_dec[idx_j, :] + b_dec   (768 = 3*256)
// ---------------------------------------------------------------------------
__global__ __launch_bounds__(256)
void dec_kernel(const float* __restrict__ Wd, const float* __restrict__ b_dec,
                float* __restrict__ Xhat)
{
    const int row = blockIdx.x;
    const int t = threadIdx.x;
    __shared__ float sv[TOPK];
    __shared__ int   si[TOPK];
    if (t < TOPK) { sv[t] = g_tv[row * TOPK + t]; si[t] = g_ti[row * TOPK + t]; }
    __syncthreads();

    float a0 = b_dec[t], a1 = b_dec[t + 256], a2 = b_dec[t + 512];
    #pragma unroll
    for (int j = 0; j < TOPK; j++) {
        const float* __restrict__ wr = Wd + (size_t)si[j] * D_DIM;
        float v = sv[j];
        a0 += v * wr[t];
        a1 += v * wr[t + 256];
        a2 += v * wr[t + 512];
    }
    float* __restrict__ xr = Xhat + (size_t)row * D_DIM;
    xr[t] = a0; xr[t + 256] = a1; xr[t + 512] = a2;
}

// ---------------------------------------------------------------------------
extern "C" void kernel_launch(void* const* d_in, const int* in_sizes, int n_in,
                              void* d_out, int out_size)
{
    const float* x     = (const float*)d_in[0];
    const float* b_pre = (const float*)d_in[1];
    const float* W_enc = (const float*)d_in[2];
    const float* b_enc = (const float*)d_in[3];
    const float* W_dec = (const float*)d_in[4];
    const float* b_dec = (const float*)d_in[5];
    float* out = (float*)d_out;

    const size_t needH = (size_t)B_ROWS * F_DIM;
    const size_t needX = (size_t)B_ROWS * D_DIM;

    float* H = nullptr;
    float* Xhat = nullptr;
    if ((size_t)out_size >= needH + needX) {        // h then x_hat (expected)
        H = out; Xhat = out + needH;
    } else if ((size_t)out_size >= needH) {          // h only
        H = out;
    } else {                                          // x_hat only: H in scratch
        cudaGetSymbolAddress((void**)&H, g_H);
        Xhat = out;
    }

    dim3 g1(B_ROWS / 128, F_DIM / 128);
    enc_gemm<<<g1, 256>>>(x, b_pre, W_enc, b_enc, H);
    topk_kernel<<<B_ROWS, 256>>>(H);
    if (Xhat) dec_kernel<<<B_ROWS, 256>>>(W_dec, b_dec, Xhat);
}

// round 6
// speedup vs baseline: 3.8883x; 3.8883x over previous
#include <cuda_runtime.h>
#include <cuda_bf16.h>
#include <cstdint>

#define B_ROWS 4096
#define D_DIM  768
#define F_DIM  24576
#define TOPK   32
#define NCAND  40

// ---------------- scratch (device globals; no runtime allocation) ----------
__device__ __nv_bfloat16 g_Hb[(size_t)B_ROWS * F_DIM];   // approx pre-acts (bf16)
__device__ float         g_WT[(size_t)F_DIM * D_DIM];    // W_enc^T fp32 (exact path)
__device__ __nv_bfloat16 g_Wb[(size_t)F_DIM * D_DIM];    // W_enc^T bf16 (mma B operand)
__device__ __nv_bfloat16 g_Xb[(size_t)B_ROWS * D_DIM];   // bf16(x - b_pre)
__device__ int   g_ci[B_ROWS * NCAND];
__device__ float g_tv[B_ROWS * TOPK];
__device__ int   g_ti[B_ROWS * TOPK];

// ---------------- helpers ---------------------------------------------------
__device__ __forceinline__ uint32_t smem_u32(const void* p) {
    uint32_t a;
    asm("{ .reg .u64 t; cvta.to.shared.u64 t, %1; cvt.u32.u64 %0, t; }" : "=r"(a) : "l"(p));
    return a;
}
__device__ __forceinline__ uint32_t pack_bf2(float lo, float hi) {
    __nv_bfloat162 h2 = __floats2bfloat162_rn(lo, hi);
    return *reinterpret_cast<uint32_t*>(&h2);
}

#define LDSM_X4(r, addr)                                                       \
    asm volatile("ldmatrix.sync.aligned.m8n8.x4.shared.b16 {%0,%1,%2,%3}, [%4];" \
        : "=r"((r)[0]), "=r"((r)[1]), "=r"((r)[2]), "=r"((r)[3]) : "r"(addr))

#define MMA16816(d, a, b0, b1)                                                 \
    asm volatile("mma.sync.aligned.m16n8k16.row.col.f32.bf16.bf16.f32 "        \
        "{%0,%1,%2,%3}, {%4,%5,%6,%7}, {%8,%9}, {%0,%1,%2,%3};"                \
        : "+f"((d)[0]), "+f"((d)[1]), "+f"((d)[2]), "+f"((d)[3])               \
        : "r"((a)[0]), "r"((a)[1]), "r"((a)[2]), "r"((a)[3]),                  \
          "r"(b0), "r"(b1))

#define CP_ASYNC16(dst, src)                                                   \
    asm volatile("cp.async.ca.shared.global [%0], [%1], 16;"                   \
                 :: "r"(dst), "l"(src) : "memory")
#define CP_COMMIT()  asm volatile("cp.async.commit_group;" ::: "memory")
#define CP_WAIT(n)   asm volatile("cp.async.wait_group %0;" :: "n"(n) : "memory")

// ---------------------------------------------------------------------------
// prep_x: Xb = bf16(x - b_pre)
// ---------------------------------------------------------------------------
__global__ void prep_x(const float* __restrict__ X, const float* __restrict__ b_pre,
                       __nv_bfloat16* __restrict__ Xb)
{
    const int idx = blockIdx.x * blockDim.x + threadIdx.x;   // B*D/4 total
    const int d4  = idx % (D_DIM / 4);
    float4 x4 = reinterpret_cast<const float4*>(X)[idx];
    float4 bp = reinterpret_cast<const float4*>(b_pre)[d4];
    uint32_t lo = pack_bf2(x4.x - bp.x, x4.y - bp.y);
    uint32_t hi = pack_bf2(x4.z - bp.z, x4.w - bp.w);
    reinterpret_cast<uint2*>(Xb)[idx] = make_uint2(lo, hi);
}

// ---------------------------------------------------------------------------
// Transpose W_enc [D, F] -> WT fp32 [F, D] and Wb bf16 [F, D]
// ---------------------------------------------------------------------------
__global__ void transpose_kernel(const float* __restrict__ W, float* __restrict__ WT,
                                 __nv_bfloat16* __restrict__ Wb)
{
    __shared__ float tile[32][33];
    const int f0 = blockIdx.x * 32, d0 = blockIdx.y * 32;
    const int tx = threadIdx.x, ty = threadIdx.y;   // 32 x 8
    #pragma unroll
    for (int i = 0; i < 4; i++)
        tile[ty + 8 * i][tx] = W[(size_t)(d0 + ty + 8 * i) * F_DIM + f0 + tx];
    __syncthreads();
    #pragma unroll
    for (int i = 0; i < 4; i++) {
        float v = tile[tx][ty + 8 * i];
        size_t o = (size_t)(f0 + ty + 8 * i) * D_DIM + d0 + tx;
        WT[o] = v;
        Wb[o] = __float2bfloat16(v);
    }
}

// ---------------------------------------------------------------------------
// Encoder GEMM via mma.sync bf16: Hb = bf16(relu(Xb @ Wb^T + b_enc))
// CTA 128x128, BK=32, 8 warps (2m x 4n), warp tile 64x32, cp.async dbl-buffer.
// ---------------------------------------------------------------------------
__global__ __launch_bounds__(256)
void enc_gemm_mma(const __nv_bfloat16* __restrict__ Xb,
                  const __nv_bfloat16* __restrict__ Wb,
                  const float* __restrict__ b_enc,
                  __nv_bfloat16* __restrict__ Hb)
{
    __shared__ __align__(16) __nv_bfloat16 As[2][128 * 40];
    __shared__ __align__(16) __nv_bfloat16 Bs[2][128 * 40];

    const int tid = threadIdx.x, wid = tid >> 5, lane = tid & 31;
    const int row0 = blockIdx.x * 128, col0 = blockIdx.y * 128;
    const int warp_m = wid >> 2, warp_n = wid & 3;

    float acc[4][4][4];
    #pragma unroll
    for (int i = 0; i < 4; i++)
        #pragma unroll
        for (int j = 0; j < 4; j++)
            #pragma unroll
            for (int q = 0; q < 4; q++) acc[i][j][q] = 0.0f;

    const uint32_t sA[2] = { smem_u32(As[0]), smem_u32(As[1]) };
    const uint32_t sB[2] = { smem_u32(Bs[0]), smem_u32(Bs[1]) };

    const int lr0 = tid >> 2, lc0 = tid & 3;
    const int lr1 = (tid + 256) >> 2, lc1 = lc0;

    #define ISSUE(c, buf) do {                                                 \
        const int _k0 = (c) * 32;                                              \
        const __nv_bfloat16* aA0 = Xb + (size_t)(row0 + lr0) * D_DIM + _k0 + lc0 * 8; \
        const __nv_bfloat16* aA1 = Xb + (size_t)(row0 + lr1) * D_DIM + _k0 + lc1 * 8; \
        const __nv_bfloat16* aB0 = Wb + (size_t)(col0 + lr0) * D_DIM + _k0 + lc0 * 8; \
        const __nv_bfloat16* aB1 = Wb + (size_t)(col0 + lr1) * D_DIM + _k0 + lc1 * 8; \
        CP_ASYNC16(sA[buf] + lr0 * 80 + lc0 * 16, aA0);                        \
        CP_ASYNC16(sA[buf] + lr1 * 80 + lc1 * 16, aA1);                        \
        CP_ASYNC16(sB[buf] + lr0 * 80 + lc0 * 16, aB0);                        \
        CP_ASYNC16(sB[buf] + lr1 * 80 + lc1 * 16, aB1);                        \
        CP_COMMIT();                                                           \
    } while (0)

    ISSUE(0, 0);

    for (int c = 0; c < 24; c++) {
        const int buf = c & 1;
        if (c + 1 < 24) { ISSUE(c + 1, buf ^ 1); CP_WAIT(1); }
        else            { CP_WAIT(0); }
        __syncthreads();

        const uint32_t sa = sA[buf], sb = sB[buf];
        #pragma unroll
        for (int ks = 0; ks < 2; ks++) {
            uint32_t a[4][4], b[2][4];
            const uint32_t koff = (uint32_t)((ks * 16 + (lane >> 4) * 8) * 2);
            #pragma unroll
            for (int mf = 0; mf < 4; mf++) {
                const uint32_t r = (uint32_t)(warp_m * 64 + mf * 16 + (lane & 15));
                LDSM_X4(a[mf], sa + r * 80 + koff);
            }
            #pragma unroll
            for (int np = 0; np < 2; np++) {
                const uint32_t r = (uint32_t)(warp_n * 32 + np * 16 + (lane & 15));
                LDSM_X4(b[np], sb + r * 80 + koff);
            }
            #pragma unroll
            for (int mf = 0; mf < 4; mf++) {
                #pragma unroll
                for (int np = 0; np < 2; np++) {
                    MMA16816(acc[mf][np * 2 + 0], a[mf], b[np][0], b[np][2]);
                    MMA16816(acc[mf][np * 2 + 1], a[mf], b[np][1], b[np][3]);
                }
            }
        }
        __syncthreads();
    }
    #undef ISSUE

    const int lr = lane >> 2, lc = (lane & 3) * 2;
    #pragma unroll
    for (int nf = 0; nf < 4; nf++) {
        const int col = col0 + warp_n * 32 + nf * 8 + lc;
        const float e0 = b_enc[col], e1 = b_enc[col + 1];
        #pragma unroll
        for (int mf = 0; mf < 4; mf++) {
            const int row = row0 + warp_m * 64 + mf * 16 + lr;
            float v0 = fmaxf(acc[mf][nf][0] + e0, 0.0f);
            float v1 = fmaxf(acc[mf][nf][1] + e1, 0.0f);
            float v2 = fmaxf(acc[mf][nf][2] + e0, 0.0f);
            float v3 = fmaxf(acc[mf][nf][3] + e1, 0.0f);
            *reinterpret_cast<uint32_t*>(Hb + (size_t)row * F_DIM + col)       = pack_bf2(v0, v1);
            *reinterpret_cast<uint32_t*>(Hb + (size_t)(row + 8) * F_DIM + col) = pack_bf2(v2, v3);
        }
    }
}

// ---------------------------------------------------------------------------
// Per-row top-NCAND candidates on bf16 approx, with per-thread top-2 cache
// (rescan only on a thread's 2nd+ win; expected ~3 rescans per block).
// ---------------------------------------------------------------------------
__global__ __launch_bounds__(256)
void select_kernel(const __nv_bfloat16* __restrict__ Hb)
{
    const int row = blockIdx.x;
    const __nv_bfloat16* __restrict__ hrow = Hb + (size_t)row * F_DIM;
    const int t = threadIdx.x;
    const int lane = t & 31, warp = t >> 5;

    __shared__ float swv[8];
    __shared__ int   swi[8];
    __shared__ int   s_ci;

    uint64_t rem0 = 0ull, rem1 = 0ull;
    float m1 = -1.0f, m2 = -1.0f;
    int   i1 = 0x7fffffff, i2 = 0x7fffffff;
    for (int j = 0; j < 96; j++) {
        float v = __bfloat162float(hrow[j * 256 + t]);
        int idx = j * 256 + t;
        if (v > m1)      { m2 = m1; i2 = i1; m1 = v; i1 = idx; }
        else if (v > m2) { m2 = v;  i2 = idx; }
    }

    for (int r = 0; r < NCAND; r++) {
        float v = m1; int id = i1;
        #pragma unroll
        for (int s = 16; s > 0; s >>= 1) {
            float ov = __shfl_down_sync(0xffffffffu, v, s);
            int   oi = __shfl_down_sync(0xffffffffu, id, s);
            if (ov > v || (ov == v && oi < id)) { v = ov; id = oi; }
        }
        if (lane == 0) { swv[warp] = v; swi[warp] = id; }
        __syncthreads();
        if (t == 0) {
            float bv = swv[0]; int bi = swi[0];
            #pragma unroll
            for (int w = 1; w < 8; w++)
                if (swv[w] > bv || (swv[w] == bv && swi[w] < bi)) { bv = swv[w]; bi = swi[w]; }
            s_ci = bi;
            g_ci[row * NCAND + r] = bi;
        }
        __syncthreads();
        const int wi = s_ci;
        if ((wi & 255) == t) {             // I own the winner
            int j = wi >> 8;
            if (j < 64) rem0 |= (1ull << j); else rem1 |= (1ull << (j - 64));
            if (i2 >= 0) { m1 = m2; i1 = i2; i2 = -1; }   // promote cached 2nd
            else {                                         // rare: full rescan
                m1 = -1.0f; m2 = -1.0f; i1 = 0x7fffffff; i2 = 0x7fffffff;
                for (int j2 = 0; j2 < 96; j2++) {
                    bool rm = (j2 < 64) ? ((rem0 >> j2) & 1ull) : ((rem1 >> (j2 - 64)) & 1ull);
                    if (rm) continue;
                    float vv = __bfloat162float(hrow[j2 * 256 + t]);
                    int idx = j2 * 256 + t;
                    if (vv > m1)      { m2 = m1; i2 = i1; m1 = vv; i1 = idx; }
                    else if (vv > m2) { m2 = vv; i2 = idx; }
                }
            }
        }
        __syncthreads();
    }
}

// ---------------------------------------------------------------------------
__global__ void zero_kernel(float4* __restrict__ p, size_t n4)
{
    size_t i = (size_t)blockIdx.x * blockDim.x + threadIdx.x;
    const size_t stride = (size_t)gridDim.x * blockDim.x;
    for (; i < n4; i += stride) p[i] = make_float4(0.f, 0.f, 0.f, 0.f);
}

// ---------------------------------------------------------------------------
// Exact recompute, BIT-IDENTICAL to the round-1 fp32 path:
// one thread per candidate, single fp32 accumulator, fmaf over k = 0..767
// ascending, then fmaxf(s + b_enc, 0). Then per-warp exact top-32 + scatter.
// 8 rows per block, 320 threads (8 x 40 candidates).
// ---------------------------------------------------------------------------
__global__ __launch_bounds__(320)
void exact_seq(const float* __restrict__ X, const float* __restrict__ b_pre,
               const float* __restrict__ WT, const float* __restrict__ b_enc,
               float* __restrict__ Hout)
{
    const int r0 = blockIdx.x * 8;
    const int t = threadIdx.x;
    const int lane = t & 31, w = t >> 5;

    __shared__ float xs[8][D_DIM];
    __shared__ float cv[8][NCAND];
    __shared__ int   ci[8][NCAND];

    for (int i = t; i < 8 * D_DIM; i += 320) {
        const int rr = i / D_DIM, k = i % D_DIM;
        xs[rr][k] = X[(size_t)(r0 + rr) * D_DIM + k] - b_pre[k];
    }
    if (t < 8 * NCAND) ci[t / NCAND][t % NCAND] = g_ci[(size_t)(r0 + t / NCAND) * NCAND + t % NCAND];
    __syncthreads();

    {   // all 320 threads: one candidate each, strict sequential fp32 chain
        const int rr = t / NCAND, c = t % NCAND;
        const int f = ci[rr][c];
        const float* __restrict__ wt = WT + (size_t)f * D_DIM;
        const float* __restrict__ xr = xs[rr];
        float s = 0.0f;
        #pragma unroll 4
        for (int k4 = 0; k4 < D_DIM / 4; k4++) {
            float4 w4 = reinterpret_cast<const float4*>(wt)[k4];
            float4 x4 = reinterpret_cast<const float4*>(xr)[k4];
            s = fmaf(w4.x, x4.x, s);
            s = fmaf(w4.y, x4.y, s);
            s = fmaf(w4.z, x4.z, s);
            s = fmaf(w4.w, x4.w, s);
        }
        cv[rr][c] = fmaxf(s + b_enc[f], 0.0f);
    }
    __syncthreads();

    // warps 0..7: exact top-32 of this row's 40 candidates (ties -> lower idx)
    if (w < 8) {
        const int row = r0 + w;
        uint64_t used = 0ull;
        for (int r2 = 0; r2 < TOPK; r2++) {
            float v = -1.0f; int idx = 0x7fffffff; int jslot = 63;
            {
                int j0 = lane;
                if (!((used >> j0) & 1ull)) { v = cv[w][j0]; idx = ci[w][j0]; jslot = j0; }
                if (lane < NCAND - 32) {
                    int j1 = 32 + lane;
                    if (!((used >> j1) & 1ull)) {
                        float v1 = cv[w][j1]; int k1 = ci[w][j1];
                        if (v1 > v || (v1 == v && k1 < idx)) { v = v1; idx = k1; jslot = j1; }
                    }
                }
            }
            #pragma unroll
            for (int s = 16; s > 0; s >>= 1) {
                float ov = __shfl_down_sync(0xffffffffu, v, s);
                int   oi = __shfl_down_sync(0xffffffffu, idx, s);
                int   oj = __shfl_down_sync(0xffffffffu, jslot, s);
                if (ov > v || (ov == v && oi < idx)) { v = ov; idx = oi; jslot = oj; }
            }
            int winj = __shfl_sync(0xffffffffu, jslot, 0);
            if (lane == 0) {
                g_tv[row * TOPK + r2] = v;
                g_ti[row * TOPK + r2] = idx;
                Hout[(size_t)row * F_DIM + idx] = v;
            }
            used |= (1ull << winj);
        }
    }
}

// ---------------------------------------------------------------------------
__global__ __launch_bounds__(256)
void dec_kernel(const float* __restrict__ Wd, const float* __restrict__ b_dec,
                float* __restrict__ Xhat)
{
    const int row = blockIdx.x;
    const int t = threadIdx.x;
    __shared__ float sv[TOPK];
    __shared__ int   si[TOPK];
    if (t < TOPK) { sv[t] = g_tv[row * TOPK + t]; si[t] = g_ti[row * TOPK + t]; }
    __syncthreads();

    float a0 = b_dec[t], a1 = b_dec[t + 256], a2 = b_dec[t + 512];
    #pragma unroll
    for (int j = 0; j < TOPK; j++) {
        const float* __restrict__ wr = Wd + (size_t)si[j] * D_DIM;
        float v = sv[j];
        a0 += v * wr[t];
        a1 += v * wr[t + 256];
        a2 += v * wr[t + 512];
    }
    float* __restrict__ xr = Xhat + (size_t)row * D_DIM;
    xr[t] = a0; xr[t + 256] = a1; xr[t + 512] = a2;
}

// ---------------------------------------------------------------------------
extern "C" void kernel_launch(void* const* d_in, const int* in_sizes, int n_in,
                              void* d_out, int out_size)
{
    const float* x     = (const float*)d_in[0];
    const float* b_pre = (const float*)d_in[1];
    const float* W_enc = (const float*)d_in[2];
    const float* b_enc = (const float*)d_in[3];
    const float* W_dec = (const float*)d_in[4];
    const float* b_dec = (const float*)d_in[5];
    float* out = (float*)d_out;

    const size_t needH = (size_t)B_ROWS * F_DIM;
    const size_t needX = (size_t)B_ROWS * D_DIM;
    float* H    = out;                            // out holds h (+ x_hat)
    float* Xhat = ((size_t)out_size >= needH + needX) ? out + needH : nullptr;

    float* WT = nullptr;          cudaGetSymbolAddress((void**)&WT, g_WT);
    __nv_bfloat16* Wb = nullptr;  cudaGetSymbolAddress((void**)&Wb, g_Wb);
    __nv_bfloat16* Xb = nullptr;  cudaGetSymbolAddress((void**)&Xb, g_Xb);
    __nv_bfloat16* Hb = nullptr;  cudaGetSymbolAddress((void**)&Hb, g_Hb);

    prep_x<<<(B_ROWS * D_DIM / 4) / 256, 256>>>(x, b_pre, Xb);
    transpose_kernel<<<dim3(F_DIM / 32, D_DIM / 32), dim3(32, 8)>>>(W_enc, WT, Wb);
    enc_gemm_mma<<<dim3(B_ROWS / 128, F_DIM / 128), 256>>>(Xb, Wb, b_enc, Hb);
    select_kernel<<<B_ROWS, 256>>>(Hb);
    zero_kernel<<<12288, 256>>>(reinterpret_cast<float4*>(H), needH / 4);
    exact_seq<<<B_ROWS / 8, 320>>>(x, b_pre, WT, b_enc, H);
    if (Xhat) dec_kernel<<<B_ROWS, 256>>>(W_dec, b_dec, Xhat);
}